// round 3
// baseline (speedup 1.0000x reference)
#include <cuda_runtime.h>
#include <math.h>

#define Bn 4
#define Hn 128
#define Wn 128
#define Cn 128
#define SLICE (Hn*Wn)              // 16384
#define NPOS (Bn*Hn*Wn)            // 65536
#define ATT_SCALE 0.08838834764831845f   // 128^-0.5

#define LDA 68        // padded ld for [row][k] chunk arrays (bank = g*4+t, conflict-free)
#define LDV 136       // padded ld for [k][n] V-style arrays (bank = t*8+g, conflict-free)
#define SMEM_BYTES 139264   // 4 * 8704 floats

// ----------------- scratch (device globals; no allocations) -----------------
__device__ __align__(128) float g_q [Bn*Cn*SLICE];   // (B,C,H,W)
__device__ __align__(128) float g_k [Bn*Cn*SLICE];   // (B,C,H,W)
__device__ __align__(128) float g_v [Bn*Cn*SLICE];   // (B,C,H,W)
__device__ __align__(128) float g_xs[NPOS*Cn];       // (B,H,W,C) sampled
__device__ __align__(128) float g_coords[NPOS*2];
__device__ __align__(128) float g_Weff[2*Cn*25];     // folded Wc2 @ Wc1
__device__ __align__(128) float g_beff[2];

extern __shared__ float smem[];

// ----------------- tf32 helpers -----------------
__device__ __forceinline__ unsigned f2tf(float x) {
    unsigned r; asm("cvt.rna.tf32.f32 %0, %1;" : "=r"(r) : "f"(x)); return r;
}
struct HL { unsigned h, l; };
__device__ __forceinline__ HL cvt_hl(float x) {
    HL o; o.h = f2tf(x);
    o.l = f2tf(x - __uint_as_float(o.h));
    return o;
}
__device__ __forceinline__ void mma8(float c[4], const unsigned a[4], unsigned b0, unsigned b1) {
    asm volatile(
        "mma.sync.aligned.m16n8k8.row.col.f32.tf32.tf32.f32 "
        "{%0,%1,%2,%3},{%4,%5,%6,%7},{%8,%9},{%0,%1,%2,%3};"
        : "+f"(c[0]), "+f"(c[1]), "+f"(c[2]), "+f"(c[3])
        : "r"(a[0]), "r"(a[1]), "r"(a[2]), "r"(a[3]), "r"(b0), "r"(b1));
}

// ----------------- smem chunk loaders (fp32 -> hi/lo tf32) -----------------
// 128 rows x 64 cols, row-major source (stride ld), into [row][64] with LDA pad
__device__ __forceinline__ void load_rm_128x64(const float* __restrict__ src, int ld,
                                               float* sh, float* sl, int tid, float mul) {
#pragma unroll
    for (int it = 0; it < 8; it++) {
        int idx = it*256 + tid;
        int r = idx >> 4, f4 = idx & 15;
        float4 v = *(const float4*)(src + (size_t)r*ld + f4*4);
        uint4 h, l; HL a;
        a = cvt_hl(v.x*mul); h.x = a.h; l.x = a.l;
        a = cvt_hl(v.y*mul); h.y = a.h; l.y = a.l;
        a = cvt_hl(v.z*mul); h.z = a.h; l.z = a.l;
        a = cvt_hl(v.w*mul); h.w = a.h; l.w = a.l;
        *(uint4*)(sh + r*LDA + f4*4) = h;
        *(uint4*)(sl + r*LDA + f4*4) = l;
    }
}
// 64 rows x 128 cols (V-style [k][n]), into LDV-padded arrays
__device__ __forceinline__ void load_rm_64x128_v(const float* __restrict__ src, int ld,
                                                 float* sh, float* sl, int tid) {
#pragma unroll
    for (int it = 0; it < 8; it++) {
        int idx = it*256 + tid;
        int r = idx >> 5, f4 = idx & 31;
        float4 v = *(const float4*)(src + (size_t)r*ld + f4*4);
        uint4 h, l; HL a;
        a = cvt_hl(v.x); h.x = a.h; l.x = a.l;
        a = cvt_hl(v.y); h.y = a.h; l.y = a.l;
        a = cvt_hl(v.z); h.z = a.h; l.z = a.l;
        a = cvt_hl(v.w); h.w = a.h; l.w = a.l;
        *(uint4*)(sh + r*LDV + f4*4) = h;
        *(uint4*)(sl + r*LDV + f4*4) = l;
    }
}

// ----------------- tf32x3 GEMM over one K=64 chunk -----------------
// MT m16-tiles, NT n8-tiles per warp. B either W-style [n][k] (LDA) or V-style [k][n] (LDV).
template<int MT, int NT, bool VSTYLE>
__device__ __forceinline__ void gemm_chunk(const float* sAh, const float* sAl,
                                           const float* sBh, const float* sBl,
                                           float (*acc)[NT][4], int m0, int n0, int g, int t) {
#pragma unroll
    for (int ks = 0; ks < 8; ks++) {
        int k0 = ks*8;
        unsigned ah[MT][4], al[MT][4];
#pragma unroll
        for (int mt = 0; mt < MT; mt++) {
            int ra = (m0 + mt*16 + g)*LDA + k0 + t;
            ah[mt][0] = __float_as_uint(sAh[ra]);
            ah[mt][1] = __float_as_uint(sAh[ra + 8*LDA]);
            ah[mt][2] = __float_as_uint(sAh[ra + 4]);
            ah[mt][3] = __float_as_uint(sAh[ra + 8*LDA + 4]);
            al[mt][0] = __float_as_uint(sAl[ra]);
            al[mt][1] = __float_as_uint(sAl[ra + 8*LDA]);
            al[mt][2] = __float_as_uint(sAl[ra + 4]);
            al[mt][3] = __float_as_uint(sAl[ra + 8*LDA + 4]);
        }
#pragma unroll
        for (int nt = 0; nt < NT; nt++) {
            unsigned bh0, bh1, bl0, bl1;
            if (VSTYLE) {
                int rb = (k0 + t)*LDV + n0 + nt*8 + g;
                bh0 = __float_as_uint(sBh[rb]); bh1 = __float_as_uint(sBh[rb + 4*LDV]);
                bl0 = __float_as_uint(sBl[rb]); bl1 = __float_as_uint(sBl[rb + 4*LDV]);
            } else {
                int rb = (n0 + nt*8 + g)*LDA + k0 + t;
                bh0 = __float_as_uint(sBh[rb]); bh1 = __float_as_uint(sBh[rb + 4]);
                bl0 = __float_as_uint(sBl[rb]); bl1 = __float_as_uint(sBl[rb + 4]);
            }
#pragma unroll
            for (int mt = 0; mt < MT; mt++) {
                mma8(acc[mt][nt], ah[mt], bh0, bh1);
                mma8(acc[mt][nt], ah[mt], bl0, bl1);
                mma8(acc[mt][nt], al[mt], bh0, bh1);
            }
        }
    }
}

// ----------------- prep: conv folding -----------------
__global__ void prep_kernel(const float* __restrict__ Wc1, const float* __restrict__ Wc2,
                            const float* __restrict__ bc1) {
    int blk = blockIdx.x, tid = threadIdx.x;
    if (blk < 25) {
        int t = blk;
        int j = tid >> 7, c = tid & 127;
        float s = 0.f;
        for (int o = 0; o < 128; o++)
            s += Wc2[j*128 + o] * Wc1[((size_t)(o*128 + c))*25 + t];
        g_Weff[(j*128 + c)*25 + t] = s;
    } else {
        if (tid < 2) {
            float s = 0.f;
            for (int o = 0; o < 128; o++) s += Wc2[tid*128 + o] * bc1[o];
            g_beff[tid] = s;
        }
    }
}

// ----------------- projection: out[b,c,h,w] = W @ src + bias (+rel) -----------------
__global__ void __launch_bounds__(256,1) proj_kernel(const float* __restrict__ x, int use_xs,
                                                     const float* __restrict__ W,
                                                     const float* __restrict__ bias,
                                                     const float* __restrict__ rel, int dst_sel) {
    float *sAh = smem, *sAl = smem + 8704, *sBh = smem + 17408, *sBl = smem + 26112;
    int tid = threadIdx.x, wid = tid >> 5, lane = tid & 31, g = lane >> 2, t = lane & 3;
    int b = blockIdx.x >> 7, h = blockIdx.x & 127;
    const float* src = (use_xs ? g_xs : x) + ((size_t)(b*128 + h))*128*128;  // [w][cin]

    float acc[2][8][4] = {};
    int m0 = (wid >> 1)*32, n0 = (wid & 1)*64;
    for (int kc = 0; kc < 2; kc++) {
        load_rm_128x64(src + kc*64, 128, sAh, sAl, tid, 1.f);
        load_rm_128x64(W   + kc*64, 128, sBh, sBl, tid, 1.f);
        __syncthreads();
        gemm_chunk<2,8,false>(sAh, sAl, sBh, sBl, acc, m0, n0, g, t);
        __syncthreads();
    }
    // stage transposed [c][w] (ld 132, conflict-free writes)
    float* stage = smem;
#pragma unroll
    for (int mt = 0; mt < 2; mt++)
#pragma unroll
        for (int nt = 0; nt < 8; nt++) {
            int m = m0 + mt*16 + g, c = n0 + nt*8 + 2*t;
            stage[c*132 + m]         = acc[mt][nt][0];
            stage[(c+1)*132 + m]     = acc[mt][nt][1];
            stage[c*132 + m + 8]     = acc[mt][nt][2];
            stage[(c+1)*132 + m + 8] = acc[mt][nt][3];
        }
    __syncthreads();
    float* dst = (dst_sel == 0 ? g_q : dst_sel == 1 ? g_k : g_v)
                 + ((size_t)b*128)*16384 + h*128;
#pragma unroll
    for (int it = 0; it < 16; it++) {
        int idx = it*256 + tid;
        int c = idx >> 5, w4 = idx & 31;
        float bv = bias[c] + (rel ? rel[c*128 + h] : 0.f);
        float4 v = *(float4*)(stage + c*132 + w4*4);
        v.x += bv; v.y += bv; v.z += bv; v.w += bv;
        *(float4*)(dst + (size_t)c*16384 + w4*4) = v;
    }
}

// ----------------- folded offset conv + sampling coordinates -----------------
__global__ void __launch_bounds__(256) offset_kernel() {
    __shared__ float tile[8*20*20];
    __shared__ float wsm[2*8*25];
    int tid = threadIdx.x;
    int ty = tid >> 4, tx = tid & 15;
    int b  = blockIdx.x >> 6;
    int t8 = blockIdx.x & 63;
    int h0 = (t8 >> 3)*16, w0 = (t8 & 7)*16;
    float acc0 = g_beff[0], acc1 = g_beff[1];
    for (int c0 = 0; c0 < 128; c0 += 8) {
        __syncthreads();
        for (int idx = tid; idx < 3200; idx += 256) {
            int cc = idx / 400, rem = idx % 400;
            int r = rem / 20, col = rem % 20;
            int hh = h0 - 2 + r, ww = w0 - 2 + col;
            float v = 0.f;
            if (hh >= 0 && hh < Hn && ww >= 0 && ww < Wn)
                v = g_q[((size_t)((b*Cn + c0 + cc)*Hn + hh))*Wn + ww];
            tile[idx] = v;
        }
        for (int idx = tid; idx < 400; idx += 256) {
            int j = idx / 200, rem = idx % 200;
            int cc = rem / 25, t = rem % 25;
            wsm[idx] = g_Weff[((j*128) + c0 + cc)*25 + t];
        }
        __syncthreads();
#pragma unroll
        for (int cc = 0; cc < 8; cc++)
#pragma unroll
            for (int kh = 0; kh < 5; kh++)
#pragma unroll
                for (int kw = 0; kw < 5; kw++) {
                    float v = tile[cc*400 + (ty + kh)*20 + tx + kw];
                    acc0 += v * wsm[      cc*25 + kh*5 + kw];
                    acc1 += v * wsm[200 + cc*25 + kh*5 + kw];
                }
    }
    float off0 = tanhf(acc0)*5.f;
    float off1 = tanhf(acc1)*5.f;
    int h = h0 + ty, w = w0 + tx;
    float xg = ((float)w + off0)*(128.f/127.f) - 0.5f;
    float yg = ((float)h + off1)*(128.f/127.f) - 0.5f;
    size_t p = ((size_t)(b*Hn + h))*Wn + w;
    g_coords[p*2]   = xg;
    g_coords[p*2+1] = yg;
}

// ----------------- bilinear gather -----------------
__global__ void __launch_bounds__(256) sample_kernel(const float* __restrict__ x) {
    int tid = threadIdx.x;
    int lane = tid & 31, wa = tid >> 5;
    int b = blockIdx.x >> 7, h = blockIdx.x & 127;
    const float* xb = x + (size_t)b*Hn*Wn*Cn;
    for (int w = wa; w < Wn; w += 8) {
        size_t p = ((size_t)(b*Hn + h))*Wn + w;
        float xg = g_coords[2*p], yg = g_coords[2*p + 1];
        float x0 = floorf(xg), y0 = floorf(yg);
        float4 out = make_float4(0.f, 0.f, 0.f, 0.f);
#pragma unroll
        for (int dy = 0; dy < 2; dy++)
#pragma unroll
            for (int dx = 0; dx < 2; dx++) {
                float xi = x0 + (float)dx, yi = y0 + (float)dy;
                float wt = (1.f - fabsf(xg - xi))*(1.f - fabsf(yg - yi));
                bool valid = (xi >= 0.f) && (xi <= 127.f) && (yi >= 0.f) && (yi <= 127.f);
                float wv = valid ? wt : 0.f;
                int ix = min(max((int)xi, 0), 127);
                int iy = min(max((int)yi, 0), 127);
                float4 src = *(const float4*)(xb + ((size_t)(iy*Wn + ix))*Cn + lane*4);
                out.x += wv*src.x; out.y += wv*src.y; out.z += wv*src.z; out.w += wv*src.w;
            }
        *(float4*)(g_xs + p*Cn + lane*4) = out;
    }
}

// ----------------- attention + fused output projection -----------------
__global__ void __launch_bounds__(256,1) attn_kernel(const float* __restrict__ Wo,
                                                     const float* __restrict__ bo,
                                                     float* __restrict__ out) {
    float *sAh = smem, *sAl = smem + 8704, *sBh = smem + 17408, *sBl = smem + 26112;
    int tid = threadIdx.x, wid = tid >> 5, lane = tid & 31, g = lane >> 2, t = lane & 3;
    int s = blockIdx.x;
    const float* qsl = g_q + (size_t)s*SLICE;
    const float* ksl = g_k + (size_t)s*SLICE;
    const float* vsl = g_v + (size_t)s*SLICE;

    // ---- scores = (q*scale) @ k^T : warp tile 16x128 (full rows per warp) ----
    float sacc[1][16][4] = {};
    int m0s = wid*16;
    for (int kc = 0; kc < 2; kc++) {
        load_rm_128x64(qsl + kc*64, 128, sAh, sAl, tid, ATT_SCALE);
        load_rm_128x64(ksl + kc*64, 128, sBh, sBl, tid, 1.f);
        __syncthreads();
        gemm_chunk<1,16,false>(sAh, sAl, sBh, sBl, sacc, m0s, 0, g, t);
        __syncthreads();
    }

    // ---- softmax: rows m0s+g and m0s+g+8, reduce over t-group (xor 1,2) ----
    float mx0 = -1e30f, mx1 = -1e30f;
#pragma unroll
    for (int nt = 0; nt < 16; nt++) {
        mx0 = fmaxf(mx0, fmaxf(sacc[0][nt][0], sacc[0][nt][1]));
        mx1 = fmaxf(mx1, fmaxf(sacc[0][nt][2], sacc[0][nt][3]));
    }
    mx0 = fmaxf(mx0, __shfl_xor_sync(~0u, mx0, 1));
    mx0 = fmaxf(mx0, __shfl_xor_sync(~0u, mx0, 2));
    mx1 = fmaxf(mx1, __shfl_xor_sync(~0u, mx1, 1));
    mx1 = fmaxf(mx1, __shfl_xor_sync(~0u, mx1, 2));
    float s0 = 0.f, s1 = 0.f;
#pragma unroll
    for (int nt = 0; nt < 16; nt++) {
        float p0 = expf(sacc[0][nt][0] - mx0); sacc[0][nt][0] = p0; s0 += p0;
        float p1 = expf(sacc[0][nt][1] - mx0); sacc[0][nt][1] = p1; s0 += p1;
        float p2 = expf(sacc[0][nt][2] - mx1); sacc[0][nt][2] = p2; s1 += p2;
        float p3 = expf(sacc[0][nt][3] - mx1); sacc[0][nt][3] = p3; s1 += p3;
    }
    s0 += __shfl_xor_sync(~0u, s0, 1); s0 += __shfl_xor_sync(~0u, s0, 2);
    s1 += __shfl_xor_sync(~0u, s1, 1); s1 += __shfl_xor_sync(~0u, s1, 2);
    float inv0 = 1.f/s0, inv1 = 1.f/s1;

    // ---- PV: warp tile 32x64 ----
    float vacc[2][8][4] = {};
    int m0 = (wid >> 1)*32, n0 = (wid & 1)*64;
    for (int kc = 0; kc < 2; kc++) {
        // store P chunk (cols kc*64..kc*64+63) into A buffers as hi/lo
        int r0 = m0s + g;
#pragma unroll
        for (int nt = kc*8; nt < kc*8 + 8; nt++) {
            int jc = nt*8 - kc*64 + 2*t;
            HL a;
            a = cvt_hl(sacc[0][nt][0]*inv0);
            sAh[r0*LDA + jc]     = __uint_as_float(a.h); sAl[r0*LDA + jc]     = __uint_as_float(a.l);
            a = cvt_hl(sacc[0][nt][1]*inv0);
            sAh[r0*LDA + jc + 1] = __uint_as_float(a.h); sAl[r0*LDA + jc + 1] = __uint_as_float(a.l);
            a = cvt_hl(sacc[0][nt][2]*inv1);
            sAh[(r0+8)*LDA + jc]     = __uint_as_float(a.h); sAl[(r0+8)*LDA + jc]     = __uint_as_float(a.l);
            a = cvt_hl(sacc[0][nt][3]*inv1);
            sAh[(r0+8)*LDA + jc + 1] = __uint_as_float(a.h); sAl[(r0+8)*LDA + jc + 1] = __uint_as_float(a.l);
        }
        load_rm_64x128_v(vsl + (size_t)kc*64*128, 128, sBh, sBl, tid);
        __syncthreads();
        gemm_chunk<2,8,true>(sAh, sAl, sBh, sBl, vacc, m0, n0, g, t);
        __syncthreads();
    }

    // ---- O = PV @ Wo^T (fused output projection) ----
    float oacc[2][8][4] = {};
    for (int kc = 0; kc < 2; kc++) {
        if ((wid & 1) == kc) {   // warps owning d-chunk kc store PV into A buffers
#pragma unroll
            for (int mt = 0; mt < 2; mt++)
#pragma unroll
                for (int nt = 0; nt < 8; nt++) {
                    int m = m0 + mt*16 + g, jc = nt*8 + 2*t;
                    HL a;
                    a = cvt_hl(vacc[mt][nt][0]);
                    sAh[m*LDA + jc]     = __uint_as_float(a.h); sAl[m*LDA + jc]     = __uint_as_float(a.l);
                    a = cvt_hl(vacc[mt][nt][1]);
                    sAh[m*LDA + jc + 1] = __uint_as_float(a.h); sAl[m*LDA + jc + 1] = __uint_as_float(a.l);
                    a = cvt_hl(vacc[mt][nt][2]);
                    sAh[(m+8)*LDA + jc]     = __uint_as_float(a.h); sAl[(m+8)*LDA + jc]     = __uint_as_float(a.l);
                    a = cvt_hl(vacc[mt][nt][3]);
                    sAh[(m+8)*LDA + jc + 1] = __uint_as_float(a.h); sAl[(m+8)*LDA + jc + 1] = __uint_as_float(a.l);
                }
        }
        load_rm_128x64(Wo + kc*64, 128, sBh, sBl, tid, 1.f);
        __syncthreads();
        gemm_chunk<2,8,false>(sAh, sAl, sBh, sBl, oacc, m0, n0, g, t);
        __syncthreads();
    }

    // ---- epilogue: out[(s*128 + i)*128 + c] = oacc + bo ----
    float* ob = out + (size_t)s*SLICE;
#pragma unroll
    for (int mt = 0; mt < 2; mt++)
#pragma unroll
        for (int nt = 0; nt < 8; nt++) {
            int m = m0 + mt*16 + g, n = n0 + nt*8 + 2*t;
            float b0 = bo[n], b1 = bo[n+1];
            *(float2*)(ob + m*128 + n)     = make_float2(oacc[mt][nt][0] + b0, oacc[mt][nt][1] + b1);
            *(float2*)(ob + (m+8)*128 + n) = make_float2(oacc[mt][nt][2] + b0, oacc[mt][nt][3] + b1);
        }
}

// ----------------- launch -----------------
extern "C" void kernel_launch(void* const* d_in, const int* in_sizes, int n_in,
                              void* d_out, int out_size) {
    const float* x   = (const float*)d_in[0];
    const float* Wq  = (const float*)d_in[2];
    const float* bq  = (const float*)d_in[3];
    const float* Wk  = (const float*)d_in[4];
    const float* bk  = (const float*)d_in[5];
    const float* Wv  = (const float*)d_in[6];
    const float* bv  = (const float*)d_in[7];
    const float* Wo  = (const float*)d_in[8];
    const float* bo  = (const float*)d_in[9];
    const float* Wc1 = (const float*)d_in[10];
    const float* bc1 = (const float*)d_in[11];
    const float* Wc2 = (const float*)d_in[12];
    const float* rb  = (const float*)d_in[13];
    float* out = (float*)d_out;

    cudaFuncSetAttribute(proj_kernel, cudaFuncAttributeMaxDynamicSharedMemorySize, SMEM_BYTES);
    cudaFuncSetAttribute(attn_kernel, cudaFuncAttributeMaxDynamicSharedMemorySize, SMEM_BYTES);

    prep_kernel  <<<26,  256>>>(Wc1, Wc2, bc1);
    proj_kernel  <<<512, 256, SMEM_BYTES>>>(x, 0, Wq, bq, nullptr, 0);
    offset_kernel<<<256, 256>>>();
    sample_kernel<<<512, 256>>>(x);
    proj_kernel  <<<512, 256, SMEM_BYTES>>>(x, 1, Wk, bk, nullptr, 1);
    proj_kernel  <<<512, 256, SMEM_BYTES>>>(x, 1, Wv, bv, rb, 2);
    attn_kernel  <<<512, 256, SMEM_BYTES>>>(Wo, bo, out);
}

// round 7
// speedup vs baseline: 1.3443x; 1.3443x over previous
#include <cuda_runtime.h>
#include <math.h>
#include <stdint.h>

#define ATT_SCALE 0.08838834764831845f   // 128^-0.5
#define PW 36                            // u32-word pitch of bf16 tiles (4 mod 32 -> conflict-free)

#define TILE_W (128*PW)                  // 4608 words per tile
#define SMEM_SZ 73728                    // 4 tiles * 18432 B

// ----------------- scratch (device globals; only referenced from device code) -----------------
__device__ __align__(128) float g_q  [4*128*16384];   // (B,C,H,W)
__device__ __align__(128) float g_k  [4*128*16384];   // (B,C,H,W)
__device__ __align__(128) float g_vT [4*128*16384];   // (B,C,W,H)
__device__ __align__(128) float g_xs [65536*128];     // (B,H,W,C)
__device__ __align__(128) float g_coords[65536*2];
__device__ __align__(128) float g_Weff[2*128*25];     // folded Wc2 @ Wc1
__device__ __align__(128) float g_beff[2];

// ----------------- helpers -----------------
static __device__ __forceinline__ void mmabf(float c[4], const unsigned a[4],
                                             unsigned b0, unsigned b1) {
    asm volatile("mma.sync.aligned.m16n8k16.row.col.f32.bf16.bf16.f32 "
        "{%0,%1,%2,%3},{%4,%5,%6,%7},{%8,%9},{%0,%1,%2,%3};"
        : "+f"(c[0]), "+f"(c[1]), "+f"(c[2]), "+f"(c[3])
        : "r"(a[0]), "r"(a[1]), "r"(a[2]), "r"(a[3]), "r"(b0), "r"(b1));
}
static __device__ __forceinline__ unsigned packh(float x0, float x1) {
    unsigned h; asm("cvt.rn.bf16x2.f32 %0,%1,%2;" : "=r"(h) : "f"(x1), "f"(x0)); return h;
}
static __device__ __forceinline__ unsigned packl(float x0, float x1, unsigned h) {
    float h0 = __uint_as_float(h << 16), h1 = __uint_as_float(h & 0xffff0000u);
    return packh(x0 - h0, x1 - h1);
}

// load a 128x64 fp32 chunk (cols kc*64..) into hi/lo bf16-pair word tiles; 256 threads
static __device__ __forceinline__ void fill_chunk(const float* __restrict__ src, int ld, int kc,
                                                  float scale, unsigned* th, unsigned* tl, int tid) {
#pragma unroll
    for (int it = 0; it < 8; it++) {
        int idx = it*256 + tid;
        int r = idx >> 4, c4 = (idx & 15)*4;
        float4 v = *(const float4*)(src + (size_t)r*ld + kc*64 + c4);
        float x0 = v.x*scale, x1 = v.y*scale, x2 = v.z*scale, x3 = v.w*scale;
        unsigned h0 = packh(x0, x1), h1 = packh(x2, x3);
        unsigned l0 = packl(x0, x1, h0), l1 = packl(x2, x3, h1);
        int o = r*PW + (c4 >> 1);
        th[o] = h0; th[o+1] = h1;
        tl[o] = l0; tl[o+1] = l1;
    }
}

// warp GEMM over one K=64 chunk: C[m0..+MT*16][n0..+NT*8] += A @ B^T (bf16x3)
template<int MT, int NT>
static __device__ __forceinline__ void wgemm(const unsigned* Ah, const unsigned* Al,
                                             const unsigned* Bh, const unsigned* Bl,
                                             int m0, int n0, int g, int tg, float (*acc)[4]) {
#pragma unroll
    for (int ks = 0; ks < 4; ks++) {
        int kw = ks*8 + tg;
        unsigned ah[MT][4], al[MT][4];
#pragma unroll
        for (int mt = 0; mt < MT; mt++) {
            int base = (m0 + mt*16 + g)*PW + kw;
            ah[mt][0] = Ah[base];     ah[mt][1] = Ah[base + 8*PW];
            ah[mt][2] = Ah[base + 4]; ah[mt][3] = Ah[base + 8*PW + 4];
            al[mt][0] = Al[base];     al[mt][1] = Al[base + 8*PW];
            al[mt][2] = Al[base + 4]; al[mt][3] = Al[base + 8*PW + 4];
        }
#pragma unroll
        for (int nt = 0; nt < NT; nt++) {
            int bb = (n0 + nt*8 + g)*PW + kw;
            unsigned bh0 = Bh[bb], bh1 = Bh[bb + 4];
            unsigned bl0 = Bl[bb], bl1 = Bl[bb + 4];
#pragma unroll
            for (int mt = 0; mt < MT; mt++) {
                mmabf(acc[mt*NT + nt], ah[mt], bh0, bh1);
                mmabf(acc[mt*NT + nt], ah[mt], bl0, bl1);
                mmabf(acc[mt*NT + nt], al[mt], bh0, bh1);
            }
        }
    }
}

// ----------------- prep: conv folding -----------------
__global__ void prep_kernel(const float* __restrict__ Wc1, const float* __restrict__ Wc2,
                            const float* __restrict__ bc1) {
    int blk = blockIdx.x, tid = threadIdx.x;
    if (blk < 25) {
        int t = blk;
        int j = tid >> 7, c = tid & 127;
        float s = 0.f;
        for (int o = 0; o < 128; o++)
            s += Wc2[j*128 + o] * Wc1[((size_t)(o*128 + c))*25 + t];
        g_Weff[(j*128 + c)*25 + t] = s;
    } else {
        if (tid < 2) {
            float s = 0.f;
            for (int o = 0; o < 128; o++) s += Wc2[tid*128 + o] * bc1[o];
            g_beff[tid] = s;
        }
    }
}

// ----------------- projection: dst[b,c,·,·] = W @ src + bias (+rel); selectors, not pointers ----
__global__ void __launch_bounds__(256) pk_kernel(const float* __restrict__ x, int src_sel,
                                                 int blk_mul, int row_mul,
                                                 const float* __restrict__ W, int dst_sel,
                                                 const float* __restrict__ bias,
                                                 const float* __restrict__ rel) {
    extern __shared__ unsigned smw[];
    unsigned *Ah = smw, *Al = smw + TILE_W, *Bh = smw + 2*TILE_W, *Bl = smw + 3*TILE_W;
    int tid = threadIdx.x, wid = tid >> 5, lane = tid & 31;
    int g = lane >> 2, tg = lane & 3;
    int b = blockIdx.x >> 7, q2 = blockIdx.x & 127;
    const float* src0 = src_sel ? g_xs : x;
    const float* src = src0 + (size_t)b*2097152 + (size_t)q2*blk_mul;
    float* dst = (dst_sel == 0) ? g_q : (dst_sel == 1) ? g_k : g_vT;

    float acc[16][4] = {};
    int m0 = (wid >> 1)*32, n0 = (wid & 1)*64;
    for (int kc = 0; kc < 2; kc++) {
        fill_chunk(src, row_mul, kc, 1.f, Ah, Al, tid);
        fill_chunk(W,   128,     kc, 1.f, Bh, Bl, tid);
        __syncthreads();
        wgemm<2,8>(Ah, Al, Bh, Bl, m0, n0, g, tg, acc);
        __syncthreads();
    }

    // stage transposed [n][m], pitch 132
    float* stage = (float*)smw;
#pragma unroll
    for (int mt = 0; mt < 2; mt++)
#pragma unroll
        for (int nt = 0; nt < 8; nt++) {
            int m = m0 + mt*16 + g, n = n0 + nt*8 + 2*tg;
            stage[n*132 + m]         = acc[mt*8+nt][0];
            stage[(n+1)*132 + m]     = acc[mt*8+nt][1];
            stage[n*132 + m + 8]     = acc[mt*8+nt][2];
            stage[(n+1)*132 + m + 8] = acc[mt*8+nt][3];
        }
    __syncthreads();

    float* db = dst + (size_t)b*2097152 + (size_t)q2*128;
#pragma unroll
    for (int it = 0; it < 16; it++) {
        int idx = it*256 + tid;
        int c = idx >> 5, m4 = (idx & 31)*4;
        float bc = bias[c];
        float4 v = *(float4*)(stage + c*132 + m4);
        if (rel) {
            float4 rv = *(const float4*)(rel + c*128 + m4);
            v.x += bc + rv.x; v.y += bc + rv.y; v.z += bc + rv.z; v.w += bc + rv.w;
        } else {
            v.x += bc; v.y += bc; v.z += bc; v.w += bc;
        }
        *(float4*)(db + (size_t)c*16384 + m4) = v;
    }
}

// ----------------- offset conv + coords -----------------
__global__ void __launch_bounds__(256) offset_kernel() {
    __shared__ float tile[8*20*20];
    __shared__ float wsm[2*8*25];
    int tid = threadIdx.x;
    int ty = tid >> 4, tx = tid & 15;
    int b  = blockIdx.x >> 6;
    int t8 = blockIdx.x & 63;
    int h0 = (t8 >> 3)*16, w0 = (t8 & 7)*16;
    float acc0 = g_beff[0], acc1 = g_beff[1];
    for (int c0 = 0; c0 < 128; c0 += 8) {
        __syncthreads();
        for (int idx = tid; idx < 3200; idx += 256) {
            int cc = idx / 400, rem = idx % 400;
            int r = rem / 20, col = rem % 20;
            int hh = h0 - 2 + r, ww = w0 - 2 + col;
            float v = 0.f;
            if (hh >= 0 && hh < 128 && ww >= 0 && ww < 128)
                v = g_q[((size_t)((b*128 + c0 + cc)*128 + hh))*128 + ww];
            tile[idx] = v;
        }
        for (int idx = tid; idx < 400; idx += 256) {
            int j = idx / 200, rem = idx % 200;
            int cc = rem / 25, t = rem % 25;
            wsm[idx] = g_Weff[((j*128) + c0 + cc)*25 + t];
        }
        __syncthreads();
#pragma unroll
        for (int cc = 0; cc < 8; cc++)
#pragma unroll
            for (int kh = 0; kh < 5; kh++)
#pragma unroll
                for (int kw = 0; kw < 5; kw++) {
                    float v = tile[cc*400 + (ty + kh)*20 + tx + kw];
                    acc0 += v * wsm[      cc*25 + kh*5 + kw];
                    acc1 += v * wsm[200 + cc*25 + kh*5 + kw];
                }
    }
    float off0 = tanhf(acc0)*5.f;
    float off1 = tanhf(acc1)*5.f;
    int h = h0 + ty, w = w0 + tx;
    size_t p = ((size_t)(b*128 + h))*128 + w;
    g_coords[p*2]   = ((float)w + off0)*(128.f/127.f) - 0.5f;
    g_coords[p*2+1] = ((float)h + off1)*(128.f/127.f) - 0.5f;
}

// ----------------- bilinear gather -----------------
__global__ void __launch_bounds__(256) sample_kernel(const float* __restrict__ x) {
    int tid = threadIdx.x;
    int lane = tid & 31, wa = tid >> 5;
    int b = blockIdx.x >> 7, h = blockIdx.x & 127;
    const float* xb = x + (size_t)b*2097152;
    for (int w = wa; w < 128; w += 8) {
        size_t p = ((size_t)(b*128 + h))*128 + w;
        float xg = g_coords[2*p], yg = g_coords[2*p + 1];
        float x0 = floorf(xg), y0 = floorf(yg);
        float4 out = make_float4(0.f, 0.f, 0.f, 0.f);
#pragma unroll
        for (int dy = 0; dy < 2; dy++)
#pragma unroll
            for (int dx = 0; dx < 2; dx++) {
                float xi = x0 + (float)dx, yi = y0 + (float)dy;
                float wt = (1.f - fabsf(xg - xi))*(1.f - fabsf(yg - yi));
                bool valid = (xi >= 0.f) && (xi <= 127.f) && (yi >= 0.f) && (yi <= 127.f);
                float wv = valid ? wt : 0.f;
                int ix = min(max((int)xi, 0), 127);
                int iy = min(max((int)yi, 0), 127);
                float4 src = *(const float4*)(xb + ((size_t)(iy*128 + ix))*128 + lane*4);
                out.x += wv*src.x; out.y += wv*src.y; out.z += wv*src.z; out.w += wv*src.w;
            }
        *(float4*)(g_xs + p*128 + lane*4) = out;
    }
}

// ----------------- attention + fused output projection -----------------
__global__ void __launch_bounds__(256) attn_kernel(const float* __restrict__ Wo,
                                                   const float* __restrict__ bo,
                                                   float* __restrict__ out) {
    extern __shared__ unsigned smw[];
    unsigned *Ah = smw, *Al = smw + TILE_W, *Bh = smw + 2*TILE_W, *Bl = smw + 3*TILE_W;
    int tid = threadIdx.x, wid = tid >> 5, lane = tid & 31;
    int g = lane >> 2, tg = lane & 3;
    int s = blockIdx.x;
    const float* qs = g_q  + (size_t)s*16384;   // [i][d]
    const float* ks = g_k  + (size_t)s*16384;   // [j][d]
    const float* vs = g_vT + (size_t)s*16384;   // [d][j]
    int m0 = wid*16;

    // ---- S = (q*scale) @ k^T : warp owns 16 full rows ----
    float sacc[16][4] = {};
    for (int kc = 0; kc < 2; kc++) {
        fill_chunk(qs, 128, kc, ATT_SCALE, Ah, Al, tid);
        fill_chunk(ks, 128, kc, 1.f,       Bh, Bl, tid);
        __syncthreads();
        wgemm<1,16>(Ah, Al, Bh, Bl, m0, 0, g, tg, sacc);
        __syncthreads();
    }

    // ---- softmax, rows m0+g and m0+g+8, reduce across quad (xor 1,2) ----
    float mx0 = -1e30f, mx1 = -1e30f;
#pragma unroll
    for (int nt = 0; nt < 16; nt++) {
        mx0 = fmaxf(mx0, fmaxf(sacc[nt][0], sacc[nt][1]));
        mx1 = fmaxf(mx1, fmaxf(sacc[nt][2], sacc[nt][3]));
    }
    mx0 = fmaxf(mx0, __shfl_xor_sync(~0u, mx0, 1)); mx0 = fmaxf(mx0, __shfl_xor_sync(~0u, mx0, 2));
    mx1 = fmaxf(mx1, __shfl_xor_sync(~0u, mx1, 1)); mx1 = fmaxf(mx1, __shfl_xor_sync(~0u, mx1, 2));
    float s0 = 0.f, s1 = 0.f;
#pragma unroll
    for (int nt = 0; nt < 16; nt++) {
        sacc[nt][0] = __expf(sacc[nt][0] - mx0); s0 += sacc[nt][0];
        sacc[nt][1] = __expf(sacc[nt][1] - mx0); s0 += sacc[nt][1];
        sacc[nt][2] = __expf(sacc[nt][2] - mx1); s1 += sacc[nt][2];
        sacc[nt][3] = __expf(sacc[nt][3] - mx1); s1 += sacc[nt][3];
    }
    s0 += __shfl_xor_sync(~0u, s0, 1); s0 += __shfl_xor_sync(~0u, s0, 2);
    s1 += __shfl_xor_sync(~0u, s1, 1); s1 += __shfl_xor_sync(~0u, s1, 2);
    float inv0 = 1.f/s0, inv1 = 1.f/s1;

    // ---- PV = P @ vT^T : P chunk -> A tiles, B = vT chunk ----
    float acc2[16][4] = {};
    for (int kc = 0; kc < 2; kc++) {
#pragma unroll
        for (int nt = 8*kc; nt < 8*kc + 8; nt++) {
            int wcol = (nt - 8*kc)*4 + tg;
            float p0 = sacc[nt][0]*inv0, p1 = sacc[nt][1]*inv0;
            float p2 = sacc[nt][2]*inv1, p3 = sacc[nt][3]*inv1;
            unsigned h0 = packh(p0, p1), h1 = packh(p2, p3);
            int o0 = (m0 + g)*PW + wcol, o1 = (m0 + g + 8)*PW + wcol;
            Ah[o0] = h0; Al[o0] = packl(p0, p1, h0);
            Ah[o1] = h1; Al[o1] = packl(p2, p3, h1);
        }
        fill_chunk(vs, 128, kc, 1.f, Bh, Bl, tid);
        __syncthreads();
        wgemm<1,16>(Ah, Al, Bh, Bl, m0, 0, g, tg, acc2);
        __syncthreads();
    }

    // ---- O = PV @ Wo^T : PV chunk -> A tiles, B = Wo chunk ----
    float acc3[16][4] = {};
    for (int kc = 0; kc < 2; kc++) {
#pragma unroll
        for (int nt = 8*kc; nt < 8*kc + 8; nt++) {
            int wcol = (nt - 8*kc)*4 + tg;
            float p0 = acc2[nt][0], p1 = acc2[nt][1];
            float p2 = acc2[nt][2], p3 = acc2[nt][3];
            unsigned h0 = packh(p0, p1), h1 = packh(p2, p3);
            int o0 = (m0 + g)*PW + wcol, o1 = (m0 + g + 8)*PW + wcol;
            Ah[o0] = h0; Al[o0] = packl(p0, p1, h0);
            Ah[o1] = h1; Al[o1] = packl(p2, p3, h1);
        }
        fill_chunk(Wo, 128, kc, 1.f, Bh, Bl, tid);
        __syncthreads();
        wgemm<1,16>(Ah, Al, Bh, Bl, m0, 0, g, tg, acc3);
        __syncthreads();
    }

    // ---- epilogue: out[s*128 + m][n] = O + bo ----
    float* ob = out + (size_t)s*16384;
#pragma unroll
    for (int nt = 0; nt < 16; nt++) {
        int n = nt*8 + 2*tg, m = m0 + g;
        float b0 = bo[n], b1 = bo[n+1];
        *(float2*)(ob + (size_t)m*128 + n)     = make_float2(acc3[nt][0] + b0, acc3[nt][1] + b1);
        *(float2*)(ob + (size_t)(m+8)*128 + n) = make_float2(acc3[nt][2] + b0, acc3[nt][3] + b1);
    }
}

// ----------------- launch -----------------
extern "C" void kernel_launch(void* const* d_in, const int* in_sizes, int n_in,
                              void* d_out, int out_size) {
    const float* x   = (const float*)d_in[0];
    const float* Wq  = (const float*)d_in[2];
    const float* bq  = (const float*)d_in[3];
    const float* Wk  = (const float*)d_in[4];
    const float* bk  = (const float*)d_in[5];
    const float* Wv  = (const float*)d_in[6];
    const float* bv  = (const float*)d_in[7];
    const float* Wo  = (const float*)d_in[8];
    const float* bo  = (const float*)d_in[9];
    const float* Wc1 = (const float*)d_in[10];
    const float* bc1 = (const float*)d_in[11];
    const float* Wc2 = (const float*)d_in[12];
    const float* rb  = (const float*)d_in[13];
    float* out = (float*)d_out;

    cudaFuncSetAttribute(pk_kernel,   cudaFuncAttributeMaxDynamicSharedMemorySize, SMEM_SZ);
    cudaFuncSetAttribute(attn_kernel, cudaFuncAttributeMaxDynamicSharedMemorySize, SMEM_SZ);

    prep_kernel  <<<26,  256>>>(Wc1, Wc2, bc1);
    pk_kernel    <<<512, 256, SMEM_SZ>>>(x, 0, 16384, 128,   Wq, 0, bq, nullptr);  // q per (b,h)
    offset_kernel<<<256, 256>>>();
    sample_kernel<<<512, 256>>>(x);
    pk_kernel    <<<512, 256, SMEM_SZ>>>(x, 1, 16384, 128,   Wk, 1, bk, nullptr);  // k per (b,h)
    pk_kernel    <<<512, 256, SMEM_SZ>>>(x, 1, 128,   16384, Wv, 2, bv, rb);       // vT per (b,w)
    attn_kernel  <<<512, 256, SMEM_SZ>>>(Wo, bo, out);
}

// round 8
// speedup vs baseline: 1.5465x; 1.1504x over previous
#include <cuda_runtime.h>
#include <math.h>
#include <stdint.h>

#define ATT_SCALE 0.08838834764831845f   // 128^-0.5
#define PW 36                            // u32-word pitch of bf16 tiles (4 mod 32 -> conflict-free)

#define TILE_W (128*PW)                  // 4608 words per tile
#define SMEM_SZ 73728                    // 4 tiles * 18432 B

// ----------------- scratch (device globals; only referenced from device code) -----------------
__device__ __align__(128) float g_q  [4*128*16384];   // (B,C,H,W)
__device__ __align__(128) float g_k  [4*128*16384];   // (B,C,H,W)
__device__ __align__(128) float g_vT [4*128*16384];   // (B,C,W,H)
__device__ __align__(128) float g_xs [65536*128];     // (B,H,W,C)
__device__ __align__(128) float g_coords[65536*2];
__device__ __align__(128) float g_Weff[2*128*25];     // folded Wc2 @ Wc1
__device__ __align__(128) float g_beff[2];
// preconverted weight tiles: [w: Wq,Wk,Wv,Wo][chunk][hi=0/lo=1]
__device__ __align__(128) unsigned g_Wth[4][2][TILE_W];
__device__ __align__(128) unsigned g_Wtl[4][2][TILE_W];

// ----------------- helpers -----------------
static __device__ __forceinline__ void mmabf(float c[4], const unsigned a[4],
                                             unsigned b0, unsigned b1) {
    asm volatile("mma.sync.aligned.m16n8k16.row.col.f32.bf16.bf16.f32 "
        "{%0,%1,%2,%3},{%4,%5,%6,%7},{%8,%9},{%0,%1,%2,%3};"
        : "+f"(c[0]), "+f"(c[1]), "+f"(c[2]), "+f"(c[3])
        : "r"(a[0]), "r"(a[1]), "r"(a[2]), "r"(a[3]), "r"(b0), "r"(b1));
}
static __device__ __forceinline__ void ldsm4(unsigned r[4], unsigned addr) {
    asm volatile("ldmatrix.sync.aligned.m8n8.x4.shared.b16 {%0,%1,%2,%3},[%4];"
        : "=r"(r[0]), "=r"(r[1]), "=r"(r[2]), "=r"(r[3]) : "r"(addr));
}
static __device__ __forceinline__ unsigned packh(float x0, float x1) {
    unsigned h; asm("cvt.rn.bf16x2.f32 %0,%1,%2;" : "=r"(h) : "f"(x1), "f"(x0)); return h;
}
static __device__ __forceinline__ unsigned packl(float x0, float x1, unsigned h) {
    float h0 = __uint_as_float(h << 16), h1 = __uint_as_float(h & 0xffff0000u);
    return packh(x0 - h0, x1 - h1);
}

// load a 128x64 fp32 chunk (cols kc*64..) into hi/lo bf16-pair word tiles; 256 threads
static __device__ __forceinline__ void fill_chunk(const float* __restrict__ src, int ld, int kc,
                                                  float scale, unsigned* th, unsigned* tl, int tid) {
#pragma unroll
    for (int it = 0; it < 8; it++) {
        int idx = it*256 + tid;
        int r = idx >> 4, c4 = (idx & 15)*4;
        float4 v = *(const float4*)(src + (size_t)r*ld + kc*64 + c4);
        float x0 = v.x*scale, x1 = v.y*scale, x2 = v.z*scale, x3 = v.w*scale;
        unsigned h0 = packh(x0, x1), h1 = packh(x2, x3);
        unsigned l0 = packl(x0, x1, h0), l1 = packl(x2, x3, h1);
        int o = r*PW + (c4 >> 1);
        th[o] = h0; th[o+1] = h1;
        tl[o] = l0; tl[o+1] = l1;
    }
}

// copy a preconverted 4608-word tile pair (global -> smem); 256 threads
static __device__ __forceinline__ void copy_tile(const unsigned* __restrict__ gh,
                                                 const unsigned* __restrict__ gl,
                                                 unsigned* th, unsigned* tl, int tid) {
#pragma unroll
    for (int it = 0; it < 5; it++) {
        int idx = it*256 + tid;
        if (idx < TILE_W/4) {
            ((uint4*)th)[idx] = ((const uint4*)gh)[idx];
            ((uint4*)tl)[idx] = ((const uint4*)gl)[idx];
        }
    }
}

// warp GEMM over one K=64 chunk via ldmatrix: C[m0..+MT*16][n0..+NT*8] += A @ B^T (bf16x3)
// byte bases of the four tiles are smem addresses (cvta'ed)
template<int MT, int NT>
static __device__ __forceinline__ void wgemm(unsigned AhB, unsigned AlB,
                                             unsigned BhB, unsigned BlB,
                                             int m0, int n0, int lane, float (*acc)[4]) {
    unsigned aoff = ((m0 + ((lane>>3)&1)*8 + (lane&7))*PW + ((lane>>4)<<2))*4;
    unsigned boff = ((n0 + (lane>>4)*8 + (lane&7))*PW + (((lane>>3)&1)<<2))*4;
#pragma unroll
    for (int ks = 0; ks < 4; ks++) {
        unsigned ka = ks*32;                      // 8 words = 32 bytes per k-step
        unsigned ah[MT][4], al[MT][4];
#pragma unroll
        for (int mt = 0; mt < MT; mt++) {
            ldsm4(ah[mt], AhB + aoff + mt*(16*PW*4) + ka);
            ldsm4(al[mt], AlB + aoff + mt*(16*PW*4) + ka);
        }
#pragma unroll
        for (int ntp = 0; ntp < NT/2; ntp++) {
            unsigned bh[4], bl[4];
            unsigned bo = boff + ntp*(16*PW*4) + ka;
            ldsm4(bh, BhB + bo);
            ldsm4(bl, BlB + bo);
#pragma unroll
            for (int mt = 0; mt < MT; mt++) {
                float* c0 = acc[mt*NT + 2*ntp];
                float* c1 = acc[mt*NT + 2*ntp + 1];
                mmabf(c0, ah[mt], bh[0], bh[1]);
                mmabf(c0, ah[mt], bl[0], bl[1]);
                mmabf(c0, al[mt], bh[0], bh[1]);
                mmabf(c1, ah[mt], bh[2], bh[3]);
                mmabf(c1, ah[mt], bl[2], bl[3]);
                mmabf(c1, al[mt], bh[2], bh[3]);
            }
        }
    }
}

// ----------------- prep: conv folding -----------------
__global__ void prep_kernel(const float* __restrict__ Wc1, const float* __restrict__ Wc2,
                            const float* __restrict__ bc1) {
    int blk = blockIdx.x, tid = threadIdx.x;
    if (blk < 25) {
        int t = blk;
        int j = tid >> 7, c = tid & 127;
        float s = 0.f;
        for (int o = 0; o < 128; o++)
            s += Wc2[j*128 + o] * Wc1[((size_t)(o*128 + c))*25 + t];
        g_Weff[(j*128 + c)*25 + t] = s;
    } else {
        if (tid < 2) {
            float s = 0.f;
            for (int o = 0; o < 128; o++) s += Wc2[tid*128 + o] * bc1[o];
            g_beff[tid] = s;
        }
    }
}

// ----------------- prepW: convert 4 weight matrices to hi/lo word tiles -----------------
__global__ void prepW_kernel(const float* __restrict__ Wq, const float* __restrict__ Wk,
                             const float* __restrict__ Wv, const float* __restrict__ Wo) {
    int blk = blockIdx.x, tid = threadIdx.x;      // 8 blocks: w*2 + kc
    int w = blk >> 1, kc = blk & 1;
    const float* W = (w == 0) ? Wq : (w == 1) ? Wk : (w == 2) ? Wv : Wo;
    fill_chunk(W, 128, kc, 1.f, g_Wth[w][kc], g_Wtl[w][kc], tid);
}

// ----------------- projection: dst[b,c,·,·] = W @ src + bias (+rel) -----------------
__global__ void __launch_bounds__(256) pk_kernel(const float* __restrict__ x, int src_sel,
                                                 int blk_mul, int row_mul,
                                                 int wsel, int dst_sel,
                                                 const float* __restrict__ bias,
                                                 const float* __restrict__ rel) {
    extern __shared__ unsigned smw[];
    unsigned *Ah = smw, *Al = smw + TILE_W, *Bh = smw + 2*TILE_W, *Bl = smw + 3*TILE_W;
    unsigned sb = (unsigned)__cvta_generic_to_shared(smw);
    int tid = threadIdx.x, wid = tid >> 5, lane = tid & 31;
    int g = lane >> 2, tg = lane & 3;
    int b = blockIdx.x >> 7, q2 = blockIdx.x & 127;
    const float* src0 = src_sel ? g_xs : x;
    const float* src = src0 + (size_t)b*2097152 + (size_t)q2*blk_mul;
    float* dst = (dst_sel == 0) ? g_q : (dst_sel == 1) ? g_k : g_vT;

    float acc[16][4] = {};
    int m0 = (wid >> 1)*32, n0 = (wid & 1)*64;
    for (int kc = 0; kc < 2; kc++) {
        fill_chunk(src, row_mul, kc, 1.f, Ah, Al, tid);
        copy_tile(g_Wth[wsel][kc], g_Wtl[wsel][kc], Bh, Bl, tid);
        __syncthreads();
        wgemm<2,8>(sb, sb + TILE_W*4, sb + 2*TILE_W*4, sb + 3*TILE_W*4, m0, n0, lane, acc);
        __syncthreads();
    }

    // stage transposed [n][m], pitch 132
    float* stage = (float*)smw;
#pragma unroll
    for (int mt = 0; mt < 2; mt++)
#pragma unroll
        for (int nt = 0; nt < 8; nt++) {
            int m = m0 + mt*16 + g, n = n0 + nt*8 + 2*tg;
            stage[n*132 + m]         = acc[mt*8+nt][0];
            stage[(n+1)*132 + m]     = acc[mt*8+nt][1];
            stage[n*132 + m + 8]     = acc[mt*8+nt][2];
            stage[(n+1)*132 + m + 8] = acc[mt*8+nt][3];
        }
    __syncthreads();

    float* db = dst + (size_t)b*2097152 + (size_t)q2*128;
#pragma unroll
    for (int it = 0; it < 16; it++) {
        int idx = it*256 + tid;
        int c = idx >> 5, m4 = (idx & 31)*4;
        float bc = bias[c];
        float4 v = *(float4*)(stage + c*132 + m4);
        if (rel) {
            float4 rv = *(const float4*)(rel + c*128 + m4);
            v.x += bc + rv.x; v.y += bc + rv.y; v.z += bc + rv.z; v.w += bc + rv.w;
        } else {
            v.x += bc; v.y += bc; v.z += bc; v.w += bc;
        }
        *(float4*)(db + (size_t)c*16384 + m4) = v;
    }
}

// ----------------- offset conv + coords -----------------
__global__ void __launch_bounds__(256) offset_kernel() {
    __shared__ float tile[8*20*20];
    __shared__ float wsm[2*8*25];
    int tid = threadIdx.x;
    int ty = tid >> 4, tx = tid & 15;
    int b  = blockIdx.x >> 6;
    int t8 = blockIdx.x & 63;
    int h0 = (t8 >> 3)*16, w0 = (t8 & 7)*16;
    float acc0 = g_beff[0], acc1 = g_beff[1];
    for (int c0 = 0; c0 < 128; c0 += 8) {
        __syncthreads();
        for (int idx = tid; idx < 3200; idx += 256) {
            int cc = idx / 400, rem = idx % 400;
            int r = rem / 20, col = rem % 20;
            int hh = h0 - 2 + r, ww = w0 - 2 + col;
            float v = 0.f;
            if (hh >= 0 && hh < 128 && ww >= 0 && ww < 128)
                v = g_q[((size_t)((b*128 + c0 + cc)*128 + hh))*128 + ww];
            tile[idx] = v;
        }
        for (int idx = tid; idx < 400; idx += 256) {
            int j = idx / 200, rem = idx % 200;
            int cc = rem / 25, t = rem % 25;
            wsm[idx] = g_Weff[((j*128) + c0 + cc)*25 + t];
        }
        __syncthreads();
#pragma unroll
        for (int cc = 0; cc < 8; cc++)
#pragma unroll
            for (int kh = 0; kh < 5; kh++)
#pragma unroll
                for (int kw = 0; kw < 5; kw++) {
                    float v = tile[cc*400 + (ty + kh)*20 + tx + kw];
                    acc0 += v * wsm[      cc*25 + kh*5 + kw];
                    acc1 += v * wsm[200 + cc*25 + kh*5 + kw];
                }
    }
    float off0 = tanhf(acc0)*5.f;
    float off1 = tanhf(acc1)*5.f;
    int h = h0 + ty, w = w0 + tx;
    size_t p = ((size_t)(b*128 + h))*128 + w;
    g_coords[p*2]   = ((float)w + off0)*(128.f/127.f) - 0.5f;
    g_coords[p*2+1] = ((float)h + off1)*(128.f/127.f) - 0.5f;
}

// ----------------- bilinear gather -----------------
__global__ void __launch_bounds__(256) sample_kernel(const float* __restrict__ x) {
    int tid = threadIdx.x;
    int lane = tid & 31, wa = tid >> 5;
    int b = blockIdx.x >> 7, h = blockIdx.x & 127;
    const float* xb = x + (size_t)b*2097152;
    for (int w = wa; w < 128; w += 8) {
        size_t p = ((size_t)(b*128 + h))*128 + w;
        float xg = g_coords[2*p], yg = g_coords[2*p + 1];
        float x0 = floorf(xg), y0 = floorf(yg);
        float4 out = make_float4(0.f, 0.f, 0.f, 0.f);
#pragma unroll
        for (int dy = 0; dy < 2; dy++)
#pragma unroll
            for (int dx = 0; dx < 2; dx++) {
                float xi = x0 + (float)dx, yi = y0 + (float)dy;
                float wt = (1.f - fabsf(xg - xi))*(1.f - fabsf(yg - yi));
                bool valid = (xi >= 0.f) && (xi <= 127.f) && (yi >= 0.f) && (yi <= 127.f);
                float wv = valid ? wt : 0.f;
                int ix = min(max((int)xi, 0), 127);
                int iy = min(max((int)yi, 0), 127);
                float4 src = *(const float4*)(xb + ((size_t)(iy*128 + ix))*128 + lane*4);
                out.x += wv*src.x; out.y += wv*src.y; out.z += wv*src.z; out.w += wv*src.w;
            }
        *(float4*)(g_xs + p*128 + lane*4) = out;
    }
}

// ----------------- attention + fused output projection -----------------
__global__ void __launch_bounds__(256) attn_kernel(const float* __restrict__ bo,
                                                   float* __restrict__ out) {
    extern __shared__ unsigned smw[];
    unsigned *Ah = smw, *Al = smw + TILE_W, *Bh = smw + 2*TILE_W, *Bl = smw + 3*TILE_W;
    unsigned sb = (unsigned)__cvta_generic_to_shared(smw);
    unsigned AhB = sb, AlB = sb + TILE_W*4, BhB = sb + 2*TILE_W*4, BlB = sb + 3*TILE_W*4;
    int tid = threadIdx.x, wid = tid >> 5, lane = tid & 31;
    int g = lane >> 2, tg = lane & 3;
    int s = blockIdx.x;
    const float* qs = g_q  + (size_t)s*16384;   // [i][d]
    const float* ks = g_k  + (size_t)s*16384;   // [j][d]
    const float* vs = g_vT + (size_t)s*16384;   // [d][j]
    int m0 = wid*16;

    // ---- S = (q*scale) @ k^T : warp owns 16 full rows ----
    float sacc[16][4] = {};
    for (int kc = 0; kc < 2; kc++) {
        fill_chunk(qs, 128, kc, ATT_SCALE, Ah, Al, tid);
        fill_chunk(ks, 128, kc, 1.f,       Bh, Bl, tid);
        __syncthreads();
        wgemm<1,16>(AhB, AlB, BhB, BlB, m0, 0, lane, sacc);
        __syncthreads();
    }

    // ---- softmax, rows m0+g and m0+g+8, reduce across quad (xor 1,2) ----
    float mx0 = -1e30f, mx1 = -1e30f;
#pragma unroll
    for (int nt = 0; nt < 16; nt++) {
        mx0 = fmaxf(mx0, fmaxf(sacc[nt][0], sacc[nt][1]));
        mx1 = fmaxf(mx1, fmaxf(sacc[nt][2], sacc[nt][3]));
    }
    mx0 = fmaxf(mx0, __shfl_xor_sync(~0u, mx0, 1)); mx0 = fmaxf(mx0, __shfl_xor_sync(~0u, mx0, 2));
    mx1 = fmaxf(mx1, __shfl_xor_sync(~0u, mx1, 1)); mx1 = fmaxf(mx1, __shfl_xor_sync(~0u, mx1, 2));
    float s0 = 0.f, s1 = 0.f;
#pragma unroll
    for (int nt = 0; nt < 16; nt++) {
        sacc[nt][0] = __expf(sacc[nt][0] - mx0); s0 += sacc[nt][0];
        sacc[nt][1] = __expf(sacc[nt][1] - mx0); s0 += sacc[nt][1];
        sacc[nt][2] = __expf(sacc[nt][2] - mx1); s1 += sacc[nt][2];
        sacc[nt][3] = __expf(sacc[nt][3] - mx1); s1 += sacc[nt][3];
    }
    s0 += __shfl_xor_sync(~0u, s0, 1); s0 += __shfl_xor_sync(~0u, s0, 2);
    s1 += __shfl_xor_sync(~0u, s1, 1); s1 += __shfl_xor_sync(~0u, s1, 2);
    float inv0 = 1.f/s0, inv1 = 1.f/s1;

    // ---- PV = P @ vT^T : P chunk -> A tiles, B = vT chunk ----
    float acc2[16][4] = {};
    for (int kc = 0; kc < 2; kc++) {
#pragma unroll
        for (int nt = 8*kc; nt < 8*kc + 8; nt++) {
            int wcol = (nt - 8*kc)*4 + tg;
            float p0 = sacc[nt][0]*inv0, p1 = sacc[nt][1]*inv0;
            float p2 = sacc[nt][2]*inv1, p3 = sacc[nt][3]*inv1;
            unsigned h0 = packh(p0, p1), h1 = packh(p2, p3);
            int o0 = (m0 + g)*PW + wcol, o1 = (m0 + g + 8)*PW + wcol;
            Ah[o0] = h0; Al[o0] = packl(p0, p1, h0);
            Ah[o1] = h1; Al[o1] = packl(p2, p3, h1);
        }
        fill_chunk(vs, 128, kc, 1.f, Bh, Bl, tid);
        __syncthreads();
        wgemm<1,16>(AhB, AlB, BhB, BlB, m0, 0, lane, acc2);
        __syncthreads();
    }

    // ---- O = PV @ Wo^T : PV chunk -> A tiles, B = preconverted Wo chunk ----
    float acc3[16][4] = {};
    for (int kc = 0; kc < 2; kc++) {
#pragma unroll
        for (int nt = 8*kc; nt < 8*kc + 8; nt++) {
            int wcol = (nt - 8*kc)*4 + tg;
            float p0 = acc2[nt][0], p1 = acc2[nt][1];
            float p2 = acc2[nt][2], p3 = acc2[nt][3];
            unsigned h0 = packh(p0, p1), h1 = packh(p2, p3);
            int o0 = (m0 + g)*PW + wcol, o1 = (m0 + g + 8)*PW + wcol;
            Ah[o0] = h0; Al[o0] = packl(p0, p1, h0);
            Ah[o1] = h1; Al[o1] = packl(p2, p3, h1);
        }
        copy_tile(g_Wth[3][kc], g_Wtl[3][kc], Bh, Bl, tid);
        __syncthreads();
        wgemm<1,16>(AhB, AlB, BhB, BlB, m0, 0, lane, acc3);
        __syncthreads();
    }

    // ---- epilogue: out[s*128 + m][n] = O + bo ----
    float* ob = out + (size_t)s*16384;
#pragma unroll
    for (int nt = 0; nt < 16; nt++) {
        int n = nt*8 + 2*tg, m = m0 + g;
        float b0 = bo[n], b1 = bo[n+1];
        *(float2*)(ob + (size_t)m*128 + n)     = make_float2(acc3[nt][0] + b0, acc3[nt][1] + b1);
        *(float2*)(ob + (size_t)(m+8)*128 + n) = make_float2(acc3[nt][2] + b0, acc3[nt][3] + b1);
    }
}

// ----------------- launch -----------------
extern "C" void kernel_launch(void* const* d_in, const int* in_sizes, int n_in,
                              void* d_out, int out_size) {
    const float* x   = (const float*)d_in[0];
    const float* Wq  = (const float*)d_in[2];
    const float* bq  = (const float*)d_in[3];
    const float* Wk  = (const float*)d_in[4];
    const float* bk  = (const float*)d_in[5];
    const float* Wv  = (const float*)d_in[6];
    const float* bv  = (const float*)d_in[7];
    const float* Wo  = (const float*)d_in[8];
    const float* bo  = (const float*)d_in[9];
    const float* Wc1 = (const float*)d_in[10];
    const float* bc1 = (const float*)d_in[11];
    const float* Wc2 = (const float*)d_in[12];
    const float* rb  = (const float*)d_in[13];
    float* out = (float*)d_out;

    cudaFuncSetAttribute(pk_kernel,   cudaFuncAttributeMaxDynamicSharedMemorySize, SMEM_SZ);
    cudaFuncSetAttribute(attn_kernel, cudaFuncAttributeMaxDynamicSharedMemorySize, SMEM_SZ);

    prep_kernel  <<<26,  256>>>(Wc1, Wc2, bc1);
    prepW_kernel <<<8,   256>>>(Wq, Wk, Wv, Wo);
    pk_kernel    <<<512, 256, SMEM_SZ>>>(x, 0, 16384, 128,   0, 0, bq, nullptr);  // q per (b,h)
    offset_kernel<<<256, 256>>>();
    sample_kernel<<<512, 256>>>(x);
    pk_kernel    <<<512, 256, SMEM_SZ>>>(x, 1, 16384, 128,   1, 1, bk, nullptr);  // k per (b,h)
    pk_kernel    <<<512, 256, SMEM_SZ>>>(x, 1, 128,   16384, 2, 2, bv, rb);       // vT per (b,w)
    attn_kernel  <<<512, 256, SMEM_SZ>>>(bo, out);
}

// round 9
// speedup vs baseline: 2.0410x; 1.3198x over previous
#include <cuda_runtime.h>
#include <math.h>
#include <stdint.h>

#define ATT_SCALE 0.08838834764831845f   // 128^-0.5
#define PW 36                            // u32-word pitch of bf16 tiles (4 mod 32 -> conflict-free)

#define TILE_W  (128*PW)                 // 4608 words per 128-row tile
#define TILEQ_W (192*PW)                 // 6912 words per 192-row tile
#define SMEM_SZ 73728                    // pk/attn: 4 x 128-row tiles
#define SMEM_Q  101376                   // qproj: 2 A-tiles + 2 192-row B-tiles (92160) / stage 192*132*4

// ----------------- scratch (device globals; only referenced from device code) -----------------
__device__ __align__(128) float g_q  [4*128*16384];   // (B,C,H,W)
__device__ __align__(128) float g_k  [4*128*16384];   // (B,C,H,W)
__device__ __align__(128) float g_vT [4*128*16384];   // (B,C,W,H)
__device__ __align__(128) float g_xs [65536*128];     // (B,H,W,C)
__device__ __align__(128) float g_z  [4*64*16384];    // 50 offset-tap projections per batch
__device__ __align__(128) float g_coords[65536*2];
__device__ __align__(128) float g_Weff[50*128];       // [jt][c] fold of Wc2@Wc1
__device__ __align__(128) float g_zbias[50];          // Weff @ bq
__device__ __align__(128) float g_beff[2];            // Wc2 @ bc1
__device__ __align__(128) float g_Wqz[192*128];       // rows 0-127 Wq, 128-177 Weff@Wq, 178-191 zero
// preconverted weight tiles
__device__ __align__(128) unsigned g_WthQ[2][TILEQ_W];
__device__ __align__(128) unsigned g_WtlQ[2][TILEQ_W];
__device__ __align__(128) unsigned g_Wth[3][2][TILE_W];   // 0=Wk, 1=Wv, 2=Wo
__device__ __align__(128) unsigned g_Wtl[3][2][TILE_W];

// ----------------- helpers -----------------
static __device__ __forceinline__ void mmabf(float c[4], const unsigned a[4],
                                             unsigned b0, unsigned b1) {
    asm volatile("mma.sync.aligned.m16n8k16.row.col.f32.bf16.bf16.f32 "
        "{%0,%1,%2,%3},{%4,%5,%6,%7},{%8,%9},{%0,%1,%2,%3};"
        : "+f"(c[0]), "+f"(c[1]), "+f"(c[2]), "+f"(c[3])
        : "r"(a[0]), "r"(a[1]), "r"(a[2]), "r"(a[3]), "r"(b0), "r"(b1));
}
static __device__ __forceinline__ void ldsm4(unsigned r[4], unsigned addr) {
    asm volatile("ldmatrix.sync.aligned.m8n8.x4.shared.b16 {%0,%1,%2,%3},[%4];"
        : "=r"(r[0]), "=r"(r[1]), "=r"(r[2]), "=r"(r[3]) : "r"(addr));
}
static __device__ __forceinline__ unsigned packh(float x0, float x1) {
    unsigned h; asm("cvt.rn.bf16x2.f32 %0,%1,%2;" : "=r"(h) : "f"(x1), "f"(x0)); return h;
}
static __device__ __forceinline__ unsigned packl(float x0, float x1, unsigned h) {
    float h0 = __uint_as_float(h << 16), h1 = __uint_as_float(h & 0xffff0000u);
    return packh(x0 - h0, x1 - h1);
}

// load a ROWSx64 fp32 chunk (cols kc*64..) into hi/lo bf16-pair word tiles; 256 threads
template<int ROWS>
static __device__ __forceinline__ void fill_chunkR(const float* __restrict__ src, int ld, int kc,
                                                   float scale, unsigned* th, unsigned* tl, int tid) {
#pragma unroll
    for (int it = 0; it < ROWS/16; it++) {
        int idx = it*256 + tid;
        int r = idx >> 4, c4 = (idx & 15)*4;
        float4 v = *(const float4*)(src + (size_t)r*ld + kc*64 + c4);
        float x0 = v.x*scale, x1 = v.y*scale, x2 = v.z*scale, x3 = v.w*scale;
        unsigned h0 = packh(x0, x1), h1 = packh(x2, x3);
        unsigned l0 = packl(x0, x1, h0), l1 = packl(x2, x3, h1);
        int o = r*PW + (c4 >> 1);
        th[o] = h0; th[o+1] = h1;
        tl[o] = l0; tl[o+1] = l1;
    }
}

// copy a preconverted NW-word tile pair (global -> smem); 256 threads
template<int NW>
static __device__ __forceinline__ void copy_tileN(const unsigned* __restrict__ gh,
                                                  const unsigned* __restrict__ gl,
                                                  unsigned* th, unsigned* tl, int tid) {
#pragma unroll
    for (int it = 0; it < (NW/4 + 255)/256; it++) {
        int idx = it*256 + tid;
        if (idx < NW/4) {
            ((uint4*)th)[idx] = ((const uint4*)gh)[idx];
            ((uint4*)tl)[idx] = ((const uint4*)gl)[idx];
        }
    }
}

// warp GEMM over one K=64 chunk via ldmatrix: C[m0..+MT*16][n0..+NT*8] += A @ B^T (bf16x3)
template<int MT, int NT>
static __device__ __forceinline__ void wgemm(unsigned AhB, unsigned AlB,
                                             unsigned BhB, unsigned BlB,
                                             int m0, int n0, int lane, float (*acc)[4]) {
    unsigned aoff = ((m0 + ((lane>>3)&1)*8 + (lane&7))*PW + ((lane>>4)<<2))*4;
    unsigned boff = ((n0 + (lane>>4)*8 + (lane&7))*PW + (((lane>>3)&1)<<2))*4;
#pragma unroll
    for (int ks = 0; ks < 4; ks++) {
        unsigned ka = ks*32;
        unsigned ah[MT][4], al[MT][4];
#pragma unroll
        for (int mt = 0; mt < MT; mt++) {
            ldsm4(ah[mt], AhB + aoff + mt*(16*PW*4) + ka);
            ldsm4(al[mt], AlB + aoff + mt*(16*PW*4) + ka);
        }
#pragma unroll
        for (int ntp = 0; ntp < NT/2; ntp++) {
            unsigned bh[4], bl[4];
            unsigned bo = boff + ntp*(16*PW*4) + ka;
            ldsm4(bh, BhB + bo);
            ldsm4(bl, BlB + bo);
#pragma unroll
            for (int mt = 0; mt < MT; mt++) {
                float* c0 = acc[mt*NT + 2*ntp];
                float* c1 = acc[mt*NT + 2*ntp + 1];
                mmabf(c0, ah[mt], bh[0], bh[1]);
                mmabf(c0, ah[mt], bl[0], bl[1]);
                mmabf(c0, al[mt], bh[0], bh[1]);
                mmabf(c1, ah[mt], bh[2], bh[3]);
                mmabf(c1, ah[mt], bl[2], bl[3]);
                mmabf(c1, al[mt], bh[2], bh[3]);
            }
        }
    }
}

// ----------------- prep: Weff fold, Wq copy, zero pad, beff -----------------
__global__ void prep_kernel(const float* __restrict__ Wq, const float* __restrict__ Wc1,
                            const float* __restrict__ Wc2, const float* __restrict__ bc1) {
    int blk = blockIdx.x, tid = threadIdx.x;
    if (blk < 50) {                  // Weff[jt][c] = sum_o Wc2[j][o]*Wc1[o][c][t]
        int j = blk / 25, t = blk % 25;
        if (tid < 128) {
            float s = 0.f;
            for (int o = 0; o < 128; o++)
                s += Wc2[j*128 + o] * Wc1[((size_t)(o*128 + tid))*25 + t];
            g_Weff[blk*128 + tid] = s;
        }
    } else {
        for (int i = tid; i < 16384; i += 256) g_Wqz[i] = Wq[i];           // rows 0-127
        for (int i = tid; i < 14*128; i += 256) g_Wqz[178*128 + i] = 0.f;  // rows 178-191
        if (tid < 2) {
            float s = 0.f;
            for (int o = 0; o < 128; o++) s += Wc2[tid*128 + o] * bc1[o];
            g_beff[tid] = s;
        }
    }
}

// ----------------- prep2: Wz = Weff @ Wq (rows 128-177), zbias = Weff @ bq -----------------
__global__ void prep2_kernel(const float* __restrict__ Wq, const float* __restrict__ bq) {
    int jt = blockIdx.x, tid = threadIdx.x;     // 50 x 128
    float s = 0.f;
    for (int c = 0; c < 128; c++) s += g_Weff[jt*128 + c] * Wq[c*128 + tid];
    g_Wqz[(128 + jt)*128 + tid] = s;
    if (tid == 0) {
        float z = 0.f;
        for (int c = 0; c < 128; c++) z += g_Weff[jt*128 + c] * bq[c];
        g_zbias[jt] = z;
    }
}

// ----------------- prepW: convert weights to hi/lo word tiles -----------------
__global__ void prepW_kernel(const float* __restrict__ Wk, const float* __restrict__ Wv,
                             const float* __restrict__ Wo) {
    int blk = blockIdx.x, tid = threadIdx.x;    // 8 blocks
    if (blk < 2) {
        fill_chunkR<192>(g_Wqz, 128, blk, 1.f, g_WthQ[blk], g_WtlQ[blk], tid);
    } else {
        int w = (blk - 2) >> 1, kc = (blk - 2) & 1;
        const float* W = (w == 0) ? Wk : (w == 1) ? Wv : Wo;
        fill_chunkR<128>(W, 128, kc, 1.f, g_Wth[w][kc], g_Wtl[w][kc], tid);
    }
}

// ----------------- qproj: [q | z] = x_slice @ [Wq;Wz]^T, N=192 -----------------
__global__ void __launch_bounds__(256) qproj_kernel(const float* __restrict__ x,
                                                    const float* __restrict__ bq) {
    extern __shared__ unsigned smw[];
    unsigned *Ah = smw, *Al = smw + TILE_W, *Bh = smw + 2*TILE_W, *Bl = smw + 2*TILE_W + TILEQ_W;
    unsigned sb = (unsigned)__cvta_generic_to_shared(smw);
    unsigned AhB = sb, AlB = sb + TILE_W*4, BhB = sb + 2*TILE_W*4, BlB = sb + (2*TILE_W + TILEQ_W)*4;
    int tid = threadIdx.x, wid = tid >> 5, lane = tid & 31;
    int g = lane >> 2, tg = lane & 3;
    int b = blockIdx.x >> 7, h = blockIdx.x & 127;
    const float* src = x + (size_t)b*2097152 + (size_t)h*16384;   // [w][cin]

    float acc[24][4] = {};
    int m0 = (wid >> 1)*32, n0 = (wid & 1)*96;
    for (int kc = 0; kc < 2; kc++) {
        fill_chunkR<128>(src, 128, kc, 1.f, Ah, Al, tid);
        copy_tileN<TILEQ_W>(g_WthQ[kc], g_WtlQ[kc], Bh, Bl, tid);
        __syncthreads();
        wgemm<2,12>(AhB, AlB, BhB, BlB, m0, n0, lane, acc);
        __syncthreads();
    }

    // stage transposed [n][m], pitch 132, 192 rows
    float* stage = (float*)smw;
#pragma unroll
    for (int mt = 0; mt < 2; mt++)
#pragma unroll
        for (int nt = 0; nt < 12; nt++) {
            int m = m0 + mt*16 + g, n = n0 + nt*8 + 2*tg;
            stage[n*132 + m]         = acc[mt*12+nt][0];
            stage[(n+1)*132 + m]     = acc[mt*12+nt][1];
            stage[n*132 + m + 8]     = acc[mt*12+nt][2];
            stage[(n+1)*132 + m + 8] = acc[mt*12+nt][3];
        }
    __syncthreads();

    // q out: (b,c,h,w), bias added
    float* qd = g_q + (size_t)b*2097152 + (size_t)h*128;
#pragma unroll
    for (int it = 0; it < 16; it++) {
        int idx = it*256 + tid;
        int c = idx >> 5, m4 = (idx & 31)*4;
        float bias = bq[c];
        float4 v = *(float4*)(stage + c*132 + m4);
        v.x += bias; v.y += bias; v.z += bias; v.w += bias;
        *(float4*)(qd + (size_t)c*16384 + m4) = v;
    }
    // z out: (b, jt, h, w), raw (zbias added in offset2)
    float* zd = g_z + (size_t)b*1048576 + (size_t)h*128;
#pragma unroll
    for (int it = 0; it < 7; it++) {
        int idx = it*256 + tid;
        if (idx < 1600) {
            int zr = idx >> 5, m4 = (idx & 31)*4;
            float4 v = *(float4*)(stage + (128 + zr)*132 + m4);
            *(float4*)(zd + (size_t)zr*16384 + m4) = v;
        }
    }
}

// ----------------- offset2: 25-tap shifted sum over z + coords -----------------
__global__ void __launch_bounds__(256) offset2_kernel() {
    int p = blockIdx.x*256 + threadIdx.x;
    int b = p >> 14, rem = p & 16383;
    int h = rem >> 7, w = rem & 127;
    const float* zb = g_z + (size_t)b*1048576;
    float a0 = g_beff[0], a1 = g_beff[1];
#pragma unroll
    for (int kh = 0; kh < 5; kh++) {
        int hh = h + kh - 2;
        if ((unsigned)hh > 127u) continue;
#pragma unroll
        for (int kw = 0; kw < 5; kw++) {
            int ww = w + kw - 2;
            if ((unsigned)ww > 127u) continue;
            int t = kh*5 + kw, sp = hh*128 + ww;
            a0 += zb[(size_t)t*16384 + sp]        + g_zbias[t];
            a1 += zb[(size_t)(25 + t)*16384 + sp] + g_zbias[25 + t];
        }
    }
    float off0 = tanhf(a0)*5.f, off1 = tanhf(a1)*5.f;
    g_coords[2*p]     = ((float)w + off0)*(128.f/127.f) - 0.5f;
    g_coords[2*p + 1] = ((float)h + off1)*(128.f/127.f) - 0.5f;
}

// ----------------- k / vT projection (N=128) -----------------
__global__ void __launch_bounds__(256) pk_kernel(const float* __restrict__ x, int src_sel,
                                                 int blk_mul, int row_mul,
                                                 int wsel, int dst_sel,
                                                 const float* __restrict__ bias,
                                                 const float* __restrict__ rel) {
    extern __shared__ unsigned smw[];
    unsigned *Ah = smw, *Al = smw + TILE_W, *Bh = smw + 2*TILE_W, *Bl = smw + 3*TILE_W;
    unsigned sb = (unsigned)__cvta_generic_to_shared(smw);
    int tid = threadIdx.x, wid = tid >> 5, lane = tid & 31;
    int g = lane >> 2, tg = lane & 3;
    int b = blockIdx.x >> 7, q2 = blockIdx.x & 127;
    const float* src0 = src_sel ? g_xs : x;
    const float* src = src0 + (size_t)b*2097152 + (size_t)q2*blk_mul;
    float* dst = (dst_sel == 0) ? g_k : g_vT;

    float acc[16][4] = {};
    int m0 = (wid >> 1)*32, n0 = (wid & 1)*64;
    for (int kc = 0; kc < 2; kc++) {
        fill_chunkR<128>(src, row_mul, kc, 1.f, Ah, Al, tid);
        copy_tileN<TILE_W>(g_Wth[wsel][kc], g_Wtl[wsel][kc], Bh, Bl, tid);
        __syncthreads();
        wgemm<2,8>(sb, sb + TILE_W*4, sb + 2*TILE_W*4, sb + 3*TILE_W*4, m0, n0, lane, acc);
        __syncthreads();
    }

    float* stage = (float*)smw;
#pragma unroll
    for (int mt = 0; mt < 2; mt++)
#pragma unroll
        for (int nt = 0; nt < 8; nt++) {
            int m = m0 + mt*16 + g, n = n0 + nt*8 + 2*tg;
            stage[n*132 + m]         = acc[mt*8+nt][0];
            stage[(n+1)*132 + m]     = acc[mt*8+nt][1];
            stage[n*132 + m + 8]     = acc[mt*8+nt][2];
            stage[(n+1)*132 + m + 8] = acc[mt*8+nt][3];
        }
    __syncthreads();

    float* db = dst + (size_t)b*2097152 + (size_t)q2*128;
#pragma unroll
    for (int it = 0; it < 16; it++) {
        int idx = it*256 + tid;
        int c = idx >> 5, m4 = (idx & 31)*4;
        float bc = bias[c];
        float4 v = *(float4*)(stage + c*132 + m4);
        if (rel) {
            float4 rv = *(const float4*)(rel + c*128 + m4);
            v.x += bc + rv.x; v.y += bc + rv.y; v.z += bc + rv.z; v.w += bc + rv.w;
        } else {
            v.x += bc; v.y += bc; v.z += bc; v.w += bc;
        }
        *(float4*)(db + (size_t)c*16384 + m4) = v;
    }
}

// ----------------- bilinear gather -----------------
__global__ void __launch_bounds__(256) sample_kernel(const float* __restrict__ x) {
    int tid = threadIdx.x;
    int lane = tid & 31, wa = tid >> 5;
    int b = blockIdx.x >> 7, h = blockIdx.x & 127;
    const float* xb = x + (size_t)b*2097152;
    for (int w = wa; w < 128; w += 8) {
        size_t p = ((size_t)(b*128 + h))*128 + w;
        float xg = g_coords[2*p], yg = g_coords[2*p + 1];
        float x0 = floorf(xg), y0 = floorf(yg);
        float4 out = make_float4(0.f, 0.f, 0.f, 0.f);
#pragma unroll
        for (int dy = 0; dy < 2; dy++)
#pragma unroll
            for (int dx = 0; dx < 2; dx++) {
                float xi = x0 + (float)dx, yi = y0 + (float)dy;
                float wt = (1.f - fabsf(xg - xi))*(1.f - fabsf(yg - yi));
                bool valid = (xi >= 0.f) && (xi <= 127.f) && (yi >= 0.f) && (yi <= 127.f);
                float wv = valid ? wt : 0.f;
                int ix = min(max((int)xi, 0), 127);
                int iy = min(max((int)yi, 0), 127);
                float4 src = *(const float4*)(xb + ((size_t)(iy*128 + ix))*128 + lane*4);
                out.x += wv*src.x; out.y += wv*src.y; out.z += wv*src.z; out.w += wv*src.w;
            }
        *(float4*)(g_xs + p*128 + lane*4) = out;
    }
}

// ----------------- attention + fused output projection -----------------
__global__ void __launch_bounds__(256) attn_kernel(const float* __restrict__ bo,
                                                   float* __restrict__ out) {
    extern __shared__ unsigned smw[];
    unsigned *Ah = smw, *Al = smw + TILE_W, *Bh = smw + 2*TILE_W, *Bl = smw + 3*TILE_W;
    unsigned sb = (unsigned)__cvta_generic_to_shared(smw);
    unsigned AhB = sb, AlB = sb + TILE_W*4, BhB = sb + 2*TILE_W*4, BlB = sb + 3*TILE_W*4;
    int tid = threadIdx.x, wid = tid >> 5, lane = tid & 31;
    int g = lane >> 2, tg = lane & 3;
    int s = blockIdx.x;
    const float* qs = g_q  + (size_t)s*16384;
    const float* ks = g_k  + (size_t)s*16384;
    const float* vs = g_vT + (size_t)s*16384;
    int m0 = wid*16;

    // ---- S = (q*scale) @ k^T ----
    float sacc[16][4] = {};
    for (int kc = 0; kc < 2; kc++) {
        fill_chunkR<128>(qs, 128, kc, ATT_SCALE, Ah, Al, tid);
        fill_chunkR<128>(ks, 128, kc, 1.f,       Bh, Bl, tid);
        __syncthreads();
        wgemm<1,16>(AhB, AlB, BhB, BlB, m0, 0, lane, sacc);
        __syncthreads();
    }

    // ---- softmax ----
    float mx0 = -1e30f, mx1 = -1e30f;
#pragma unroll
    for (int nt = 0; nt < 16; nt++) {
        mx0 = fmaxf(mx0, fmaxf(sacc[nt][0], sacc[nt][1]));
        mx1 = fmaxf(mx1, fmaxf(sacc[nt][2], sacc[nt][3]));
    }
    mx0 = fmaxf(mx0, __shfl_xor_sync(~0u, mx0, 1)); mx0 = fmaxf(mx0, __shfl_xor_sync(~0u, mx0, 2));
    mx1 = fmaxf(mx1, __shfl_xor_sync(~0u, mx1, 1)); mx1 = fmaxf(mx1, __shfl_xor_sync(~0u, mx1, 2));
    float s0 = 0.f, s1 = 0.f;
#pragma unroll
    for (int nt = 0; nt < 16; nt++) {
        sacc[nt][0] = __expf(sacc[nt][0] - mx0); s0 += sacc[nt][0];
        sacc[nt][1] = __expf(sacc[nt][1] - mx0); s0 += sacc[nt][1];
        sacc[nt][2] = __expf(sacc[nt][2] - mx1); s1 += sacc[nt][2];
        sacc[nt][3] = __expf(sacc[nt][3] - mx1); s1 += sacc[nt][3];
    }
    s0 += __shfl_xor_sync(~0u, s0, 1); s0 += __shfl_xor_sync(~0u, s0, 2);
    s1 += __shfl_xor_sync(~0u, s1, 1); s1 += __shfl_xor_sync(~0u, s1, 2);
    float inv0 = 1.f/s0, inv1 = 1.f/s1;

    // ---- PV = P @ vT^T ----
    float acc2[16][4] = {};
    for (int kc = 0; kc < 2; kc++) {
#pragma unroll
        for (int nt = 8*kc; nt < 8*kc + 8; nt++) {
            int wcol = (nt - 8*kc)*4 + tg;
            float p0 = sacc[nt][0]*inv0, p1 = sacc[nt][1]*inv0;
            float p2 = sacc[nt][2]*inv1, p3 = sacc[nt][3]*inv1;
            unsigned h0 = packh(p0, p1), h1 = packh(p2, p3);
            int o0 = (m0 + g)*PW + wcol, o1 = (m0 + g + 8)*PW + wcol;
            Ah[o0] = h0; Al[o0] = packl(p0, p1, h0);
            Ah[o1] = h1; Al[o1] = packl(p2, p3, h1);
        }
        fill_chunkR<128>(vs, 128, kc, 1.f, Bh, Bl, tid);
        __syncthreads();
        wgemm<1,16>(AhB, AlB, BhB, BlB, m0, 0, lane, acc2);
        __syncthreads();
    }

    // ---- O = PV @ Wo^T ----
    float acc3[16][4] = {};
    for (int kc = 0; kc < 2; kc++) {
#pragma unroll
        for (int nt = 8*kc; nt < 8*kc + 8; nt++) {
            int wcol = (nt - 8*kc)*4 + tg;
            float p0 = acc2[nt][0], p1 = acc2[nt][1];
            float p2 = acc2[nt][2], p3 = acc2[nt][3];
            unsigned h0 = packh(p0, p1), h1 = packh(p2, p3);
            int o0 = (m0 + g)*PW + wcol, o1 = (m0 + g + 8)*PW + wcol;
            Ah[o0] = h0; Al[o0] = packl(p0, p1, h0);
            Ah[o1] = h1; Al[o1] = packl(p2, p3, h1);
        }
        copy_tileN<TILE_W>(g_Wth[2][kc], g_Wtl[2][kc], Bh, Bl, tid);
        __syncthreads();
        wgemm<1,16>(AhB, AlB, BhB, BlB, m0, 0, lane, acc3);
        __syncthreads();
    }

    // ---- epilogue ----
    float* ob = out + (size_t)s*16384;
#pragma unroll
    for (int nt = 0; nt < 16; nt++) {
        int n = nt*8 + 2*tg, m = m0 + g;
        float b0 = bo[n], b1 = bo[n+1];
        *(float2*)(ob + (size_t)m*128 + n)     = make_float2(acc3[nt][0] + b0, acc3[nt][1] + b1);
        *(float2*)(ob + (size_t)(m+8)*128 + n) = make_float2(acc3[nt][2] + b0, acc3[nt][3] + b1);
    }
}

// ----------------- launch -----------------
extern "C" void kernel_launch(void* const* d_in, const int* in_sizes, int n_in,
                              void* d_out, int out_size) {
    const float* x   = (const float*)d_in[0];
    const float* Wq  = (const float*)d_in[2];
    const float* bq  = (const float*)d_in[3];
    const float* Wk  = (const float*)d_in[4];
    const float* bk  = (const float*)d_in[5];
    const float* Wv  = (const float*)d_in[6];
    const float* bv  = (const float*)d_in[7];
    const float* Wo  = (const float*)d_in[8];
    const float* bo  = (const float*)d_in[9];
    const float* Wc1 = (const float*)d_in[10];
    const float* bc1 = (const float*)d_in[11];
    const float* Wc2 = (const float*)d_in[12];
    const float* rb  = (const float*)d_in[13];
    float* out = (float*)d_out;

    cudaFuncSetAttribute(qproj_kernel, cudaFuncAttributeMaxDynamicSharedMemorySize, SMEM_Q);
    cudaFuncSetAttribute(pk_kernel,    cudaFuncAttributeMaxDynamicSharedMemorySize, SMEM_SZ);
    cudaFuncSetAttribute(attn_kernel,  cudaFuncAttributeMaxDynamicSharedMemorySize, SMEM_SZ);

    prep_kernel   <<<51,  256>>>(Wq, Wc1, Wc2, bc1);
    prep2_kernel  <<<50,  128>>>(Wq, bq);
    prepW_kernel  <<<8,   256>>>(Wk, Wv, Wo);
    qproj_kernel  <<<512, 256, SMEM_Q>>>(x, bq);
    offset2_kernel<<<256, 256>>>();
    sample_kernel <<<512, 256>>>(x);
    pk_kernel     <<<512, 256, SMEM_SZ>>>(x, 1, 16384, 128,   0, 0, bk, nullptr);  // k per (b,h)
    pk_kernel     <<<512, 256, SMEM_SZ>>>(x, 1, 128,   16384, 1, 1, bv, rb);       // vT per (b,w)
    attn_kernel   <<<512, 256, SMEM_SZ>>>(bo, out);
}